// round 13
// baseline (speedup 1.0000x reference)
#include <cuda_runtime.h>
#include <math.h>
#include <stdint.h>

// ---------------- problem constants ----------------
#define NN     100000      // nodes
#define NEDGE  1600000     // edges
#define NELBL  200000      // edge-label pairs
#define HF     128         // feature width
#define HLW    256         // LSTM hidden
#define NLAY   4           // layers in jumping knowledge (N_LAYERS+1)
#define GW     1024        // 4*HLW gates
#define BN_EPS 1e-5f
#define TSTRIDE (128 * 36) // one smem tile in words

// ---------------- scratch (__device__ globals; total ~975 MB < 2GB link limit) ----
__device__ float g_HS [NLAY * NN * HF];
__device__ float g_T  [NN * HF];
__device__ float g_G  [NN * GW];          // pred gather [EL,256] + Z1
__device__ float g_HA [NN * HLW];
__device__ float g_HB [NN * HLW];
__device__ float g_Cst[NN * HLW];
__device__ float g_dinv[NN];
__device__ float g_logit[NLAY * NN];
__device__ float g_sum[HF];
__device__ float g_ssq[HF];

// ---------------- small utility kernels ----------------
__global__ void zero_kernel(float* p, long long n) {
    long long i = (long long)blockIdx.x * blockDim.x + threadIdx.x;
    long long stride = (long long)gridDim.x * blockDim.x;
    for (; i < n; i += stride) p[i] = 0.f;
}

__global__ void deg_kernel(const int* __restrict__ dst, float* __restrict__ deg, int E) {
    int i = blockIdx.x * blockDim.x + threadIdx.x;
    int stride = gridDim.x * blockDim.x;
    for (; i < E; i += stride) atomicAdd(&deg[dst[i]], 1.f);
}

__global__ void dinv_kernel(float* d, int n) {
    int i = blockIdx.x * blockDim.x + threadIdx.x;
    if (i < n) d[i] = rsqrtf(d[i] + 1.f);
}

template<bool BIAS>
__global__ void prop_init_kernel(float* __restrict__ out, const float* __restrict__ in,
                                 const float* __restrict__ dinv, const float* __restrict__ bias,
                                 int n_nodes) {
    long long i = (long long)blockIdx.x * blockDim.x + threadIdx.x;
    long long total = (long long)n_nodes * HF;
    long long stride = (long long)gridDim.x * blockDim.x;
    for (; i < total; i += stride) {
        int n = (int)(i >> 7);
        int c = (int)(i & 127);
        float dv = dinv[n];
        float v = dv * dv * in[i];
        if (BIAS) v += bias[c];
        out[i] = v;
    }
}

__global__ void prop_edge_kernel(const float* __restrict__ in, float* __restrict__ out,
                                 const int* __restrict__ src, const int* __restrict__ dst,
                                 const float* __restrict__ dinv, int E) {
    int warp = (blockIdx.x * blockDim.x + threadIdx.x) >> 5;
    int lane = threadIdx.x & 31;
    if (warp >= E) return;
    int s = src[warp], d = dst[warp];
    float nrm = dinv[s] * dinv[d];
    const float4* ip = (const float4*)(in + (size_t)s * HF);
    float* op = out + (size_t)d * HF;
    float4 v = ip[lane];
    atomicAdd(op + lane * 4 + 0, nrm * v.x);
    atomicAdd(op + lane * 4 + 1, nrm * v.y);
    atomicAdd(op + lane * 4 + 2, nrm * v.z);
    atomicAdd(op + lane * 4 + 3, nrm * v.w);
}

// ---------------- batchnorm ----------------
template<bool RELU>
__global__ void bn_stats_kernel(const float* __restrict__ X, float* __restrict__ sum,
                                float* __restrict__ ssq, int M) {
    int c = threadIdx.x;
    int r0 = blockIdx.x * 64;
    int r1 = min(r0 + 64, M);
    float s = 0.f, q = 0.f;
    for (int r = r0; r < r1; r++) {
        float v = X[(size_t)r * HF + c];
        if (RELU) v = fmaxf(v, 0.f);
        s += v; q += v * v;
    }
    atomicAdd(&sum[c], s);
    atomicAdd(&ssq[c], q);
}

template<bool RELU>
__global__ void bn_apply_kernel(float* __restrict__ X, const float* __restrict__ sum,
                                const float* __restrict__ ssq, const float* __restrict__ gamma,
                                const float* __restrict__ beta, int M) {
    long long i = (long long)blockIdx.x * blockDim.x + threadIdx.x;
    long long total = (long long)M * HF;
    long long stride = (long long)gridDim.x * blockDim.x;
    float invM = 1.f / (float)M;
    for (; i < total; i += stride) {
        int c = (int)(i & 127);
        float mu = sum[c] * invM;
        float var = ssq[c] * invM - mu * mu;
        float v = X[i];
        if (RELU) v = fmaxf(v, 0.f);
        X[i] = (v - mu) * rsqrtf(var + BN_EPS) * gamma[c] + beta[c];
    }
}

// ---------------- tensor-core helpers ----------------
__device__ __forceinline__ uint32_t f2t(float f) {
    uint32_t u;
    asm("cvt.rna.tf32.f32 %0, %1;" : "=r"(u) : "f"(f));
    return u;
}

__device__ __forceinline__ void mma_tf32(float* c, const uint32_t* a, const uint32_t* b) {
    asm volatile(
        "mma.sync.aligned.m16n8k8.row.col.f32.tf32.tf32.f32 "
        "{%0,%1,%2,%3},{%4,%5,%6,%7},{%8,%9},{%0,%1,%2,%3};"
        : "+f"(c[0]), "+f"(c[1]), "+f"(c[2]), "+f"(c[3])
        : "r"(a[0]), "r"(a[1]), "r"(a[2]), "r"(a[3]), "r"(b[0]), "r"(b[1]));
}

__device__ __forceinline__ float sigmoidf(float x) { return 1.f / (1.f + expf(-x)); }

// ---------------- generic tf32 GEMM (conv stack + pred1) ----------------
template<bool BT, bool ACC, bool RELU, bool BIAS>
__global__ void __launch_bounds__(256) tgemm_kernel(
    const float* __restrict__ A, const float* __restrict__ B,
    const float* __restrict__ bias, float* __restrict__ C,
    int M, int N, int K) {
    __shared__ uint32_t As[128][36];
    __shared__ uint32_t Bs[128][36];
    int tid = threadIdx.x;
    int warp = tid >> 5, lane = tid & 31;
    int gid = lane >> 2, tig = lane & 3;
    int wm = (warp & 1) * 64;
    int wn = (warp >> 1) * 32;
    int row0 = blockIdx.y * 128;
    int col0 = blockIdx.x * 128;

    float c[4][4][4] = {};

    for (int k0 = 0; k0 < K; k0 += 32) {
        {
            int r = tid >> 3;
            int cc = (tid & 7) * 4;
            #pragma unroll
            for (int p = 0; p < 4; p++) {
                int rr = p * 32 + r;
                int gr = row0 + rr;
                float4 v = (gr < M) ? *(const float4*)(A + (size_t)gr * K + k0 + cc)
                                    : make_float4(0.f, 0.f, 0.f, 0.f);
                *(uint4*)&As[rr][cc] = make_uint4(f2t(v.x), f2t(v.y), f2t(v.z), f2t(v.w));
            }
        }
        if (BT) {
            int r = tid >> 3;
            int cc = (tid & 7) * 4;
            #pragma unroll
            for (int p = 0; p < 4; p++) {
                int rr = p * 32 + r;
                float4 v = *(const float4*)(B + (size_t)(col0 + rr) * K + k0 + cc);
                *(uint4*)&Bs[rr][cc] = make_uint4(f2t(v.x), f2t(v.y), f2t(v.z), f2t(v.w));
            }
        } else {
            int r = tid >> 5;
            int cc = (tid & 31) * 4;
            #pragma unroll
            for (int p = 0; p < 4; p++) {
                int kk = p * 8 + r;
                float4 v = *(const float4*)(B + (size_t)(k0 + kk) * N + col0 + cc);
                Bs[cc + 0][kk] = f2t(v.x);
                Bs[cc + 1][kk] = f2t(v.y);
                Bs[cc + 2][kk] = f2t(v.z);
                Bs[cc + 3][kk] = f2t(v.w);
            }
        }
        __syncthreads();
        #pragma unroll
        for (int ks = 0; ks < 4; ks++) {
            int kk = ks * 8;
            uint32_t a[4][4], b[4][2];
            #pragma unroll
            for (int mi = 0; mi < 4; mi++) {
                int rr = wm + mi * 16 + gid;
                a[mi][0] = As[rr][kk + tig];
                a[mi][1] = As[rr + 8][kk + tig];
                a[mi][2] = As[rr][kk + tig + 4];
                a[mi][3] = As[rr + 8][kk + tig + 4];
            }
            #pragma unroll
            for (int ni = 0; ni < 4; ni++) {
                int nn = wn + ni * 8 + gid;
                b[ni][0] = Bs[nn][kk + tig];
                b[ni][1] = Bs[nn][kk + tig + 4];
            }
            #pragma unroll
            for (int mi = 0; mi < 4; mi++)
                #pragma unroll
                for (int ni = 0; ni < 4; ni++)
                    mma_tf32(c[mi][ni], a[mi], b[ni]);
        }
        __syncthreads();
    }

    #pragma unroll
    for (int mi = 0; mi < 4; mi++) {
        int r_lo = row0 + wm + mi * 16 + gid;
        int r_hi = r_lo + 8;
        #pragma unroll
        for (int ni = 0; ni < 4; ni++) {
            int cb = col0 + wn + ni * 8 + tig * 2;
            #pragma unroll
            for (int q = 0; q < 4; q++) {
                int gr = (q < 2) ? r_lo : r_hi;
                int gc = cb + (q & 1);
                if (gr >= M) continue;
                float v = c[mi][ni][q];
                if (BIAS) v += bias[gc];
                size_t off = (size_t)gr * N + gc;
                if (ACC) v += C[off];
                if (RELU) v = fmaxf(v, 0.f);
                C[off] = v;
            }
        }
    }
}

// ---------------- fused LSTM step (tf32, DOUBLE-BUFFERED, reg-prefetch) ----
// Round-12 tf32 step + round-11 double-buffer schedule: stores for tile it+1
// go to the buffer whose compute finished at it-1, so stores overlap compute
// and the prefetched loads get a full iteration to land. One sync/iteration.
// Dynamic smem: 2 A tiles + 2 B tiles (4*TSTRIDE words) + bias(128) + attw(32).
__global__ void __launch_bounds__(256) lstm_step_kernel(
    const float* __restrict__ X, const float* __restrict__ Hprev,
    float* __restrict__ Hnext, float* __restrict__ Cst,
    const float* __restrict__ w_ih, const float* __restrict__ w_hh,
    const float* __restrict__ b_ih, const float* __restrict__ b_hh,
    const float* __restrict__ attw, float* __restrict__ logit, int M) {
    extern __shared__ uint32_t sm[];
    uint32_t* AsB = sm;                          // [2][128][36]
    uint32_t* BsB = sm + 2 * TSTRIDE;            // [2][128][36]
    float* bias_s = (float*)(sm + 4 * TSTRIDE);  // [128]
    float* attw_s = bias_s + 128;                // [32]

    int tid = threadIdx.x;
    int warp = tid >> 5, lane = tid & 31;
    int gid = lane >> 2, tig = lane & 3;
    int wm = (warp & 1) * 64;
    int wn = (warp >> 1) * 32;
    int row0 = blockIdx.y * 128;
    int col0 = blockIdx.x * 128;

    if (tid < 128) {
        int oc = col0 + tid;
        int pr = (oc & 3) * 256 + (oc >> 2);
        bias_s[tid] = b_ih[pr] + b_hh[pr];
        if (tid < 32) attw_s[tid] = attw[(col0 >> 2) + tid];
    }

    int ldr = tid >> 3;              // 0..31
    int ldc = (tid & 7) * 4;         // 0,4,...,28
    float4 ra[4], rb[4];
    int prw[4];
    #pragma unroll
    for (int p = 0; p < 4; p++) {
        int oc = col0 + p * 32 + ldr;
        prw[p] = (oc & 3) * 256 + (oc >> 2);
    }

    float c[4][4][4] = {};

    #define LOAD_TILE(IT) do {                                                          \
        int k0_ = (IT) * 32;                                                            \
        const float* Asrc_; int Ak_, kk0_;                                              \
        if (k0_ < 128) { Asrc_ = X; Ak_ = HF; kk0_ = k0_; }                             \
        else           { Asrc_ = Hprev; Ak_ = HLW; kk0_ = k0_ - 128; }                  \
        _Pragma("unroll")                                                               \
        for (int p = 0; p < 4; p++) {                                                   \
            int gr_ = row0 + p * 32 + ldr;                                              \
            ra[p] = (gr_ < M) ? *(const float4*)(Asrc_ + (size_t)gr_ * Ak_ + kk0_ + ldc)\
                              : make_float4(0.f, 0.f, 0.f, 0.f);                        \
            rb[p] = (k0_ < 128)                                                         \
                ? *(const float4*)(w_ih + (size_t)prw[p] * HF + k0_ + ldc)              \
                : *(const float4*)(w_hh + (size_t)prw[p] * HLW + (k0_ - 128) + ldc);    \
        }                                                                               \
    } while (0)

    #define STORE_TILE(BUF) do {                                                        \
        uint32_t* A_ = AsB + (BUF) * TSTRIDE;                                           \
        uint32_t* B_ = BsB + (BUF) * TSTRIDE;                                           \
        _Pragma("unroll")                                                               \
        for (int p = 0; p < 4; p++) {                                                   \
            int rr_ = p * 32 + ldr;                                                     \
            *(float4*)&A_[rr_ * 36 + ldc] = ra[p];                                      \
            *(float4*)&B_[rr_ * 36 + ldc] = rb[p];                                      \
        }                                                                               \
    } while (0)

    // ---- prologue ----
    LOAD_TILE(0);
    STORE_TILE(0);
    LOAD_TILE(1);        // lands during iteration 0's compute
    __syncthreads();     // buf0 + bias_s visible

    for (int it = 0; it < 12; it++) {
        int buf = it & 1;
        if (it + 1 < 12) {
            STORE_TILE(buf ^ 1);            // other buffer's compute ended at it-1
            if (it + 2 < 12) LOAD_TILE(it + 2);
        }
        uint32_t* As = AsB + buf * TSTRIDE;
        uint32_t* Bs = BsB + buf * TSTRIDE;
        #pragma unroll
        for (int ks = 0; ks < 4; ks++) {
            int kk = ks * 8;
            uint32_t a[4][4], b[4][2];
            #pragma unroll
            for (int mi = 0; mi < 4; mi++) {
                int rr = wm + mi * 16 + gid;
                a[mi][0] = As[rr * 36 + kk + tig];
                a[mi][1] = As[(rr + 8) * 36 + kk + tig];
                a[mi][2] = As[rr * 36 + kk + tig + 4];
                a[mi][3] = As[(rr + 8) * 36 + kk + tig + 4];
            }
            #pragma unroll
            for (int ni = 0; ni < 4; ni++) {
                int nn = wn + ni * 8 + gid;
                b[ni][0] = Bs[nn * 36 + kk + tig];
                b[ni][1] = Bs[nn * 36 + kk + tig + 4];
            }
            #pragma unroll
            for (int mi = 0; mi < 4; mi++)
                #pragma unroll
                for (int ni = 0; ni < 4; ni++)
                    mma_tf32(c[mi][ni], a[mi], b[ni]);
        }
        __syncthreads();
    }
    #undef LOAD_TILE
    #undef STORE_TILE

    // --- fused LSTM cell epilogue ---
    int odd = tig & 1;
    #pragma unroll
    for (int mi = 0; mi < 4; mi++) {
        int r_lo = row0 + wm + mi * 16 + gid;
        int row = odd ? (r_lo + 8) : r_lo;
        float lp = 0.f;
        #pragma unroll
        for (int ni = 0; ni < 4; ni++) {
            int cb = wn + ni * 8 + tig * 2;
            float q0 = c[mi][ni][0] + bias_s[cb];
            float q1 = c[mi][ni][1] + bias_s[cb + 1];
            float q2 = c[mi][ni][2] + bias_s[cb];
            float q3 = c[mi][ni][3] + bias_s[cb + 1];
            float r0 = __shfl_xor_sync(0xFFFFFFFFu, odd ? q0 : q2, 1);
            float r1 = __shfl_xor_sync(0xFFFFFFFFu, odd ? q1 : q3, 1);
            float gi, gf, gg, go;
            int jl;
            if (!odd) { gi = q0; gf = q1; gg = r0; go = r1; jl = cb >> 2; }
            else      { gi = r0; gf = r1; gg = q2; go = q3; jl = (cb - 2) >> 2; }
            if (row < M) {
                int jg = (col0 >> 2) + jl;
                size_t off = (size_t)row * HLW + jg;
                float cn = sigmoidf(gf) * Cst[off] + sigmoidf(gi) * tanhf(gg);
                float hn = sigmoidf(go) * tanhf(cn);
                Cst[off] = cn;
                Hnext[off] = hn;
                lp += hn * attw_s[jl];
            }
        }
        lp += __shfl_xor_sync(0xFFFFFFFFu, lp, 2);
        if (tig < 2 && row < M) atomicAdd(&logit[row], lp);
    }
}

// ---------------- jumping-knowledge attention combine ----------------
__global__ void jk_kernel(const float* __restrict__ HS, const float* __restrict__ logit,
                          float* __restrict__ jk, int M) {
    int n = blockIdx.x;
    int c = threadIdx.x;  // 128
    float l0 = logit[0 * NN + n], l1 = logit[1 * NN + n];
    float l2 = logit[2 * NN + n], l3 = logit[3 * NN + n];
    float m = fmaxf(fmaxf(l0, l1), fmaxf(l2, l3));
    float e0 = expf(l0 - m), e1 = expf(l1 - m), e2 = expf(l2 - m), e3 = expf(l3 - m);
    float inv = 1.f / (e0 + e1 + e2 + e3);
    size_t off = (size_t)n * HF + c;
    size_t ls = (size_t)M * HF;
    float v = e0 * HS[off] + e1 * HS[ls + off] + e2 * HS[2 * ls + off] + e3 * HS[3 * ls + off];
    jk[off] = v * inv;
}

// ---------------- edge predictor ----------------
__global__ void gather_concat_kernel(const float* __restrict__ jk, const int* __restrict__ rows,
                                     const int* __restrict__ cols, float* __restrict__ out, int EL) {
    int e = blockIdx.x;
    int t = threadIdx.x;  // 128
    if (e >= EL) return;
    out[(size_t)e * 256 + t]       = jk[(size_t)rows[e] * HF + t];
    out[(size_t)e * 256 + 128 + t] = jk[(size_t)cols[e] * HF + t];
}

__global__ void pred_final_kernel(const float* __restrict__ Z1, const float* __restrict__ sum,
                                  const float* __restrict__ ssq, const float* __restrict__ gamma,
                                  const float* __restrict__ beta, const float* __restrict__ w2,
                                  const float* __restrict__ b2_ptr, float* __restrict__ out, int EL) {
    int e = blockIdx.x;
    int c = threadIdx.x;  // 128
    float invM = 1.f / (float)EL;
    float mu = sum[c] * invM;
    float var = ssq[c] * invM - mu * mu;
    float z = (Z1[(size_t)e * HF + c] - mu) * rsqrtf(var + BN_EPS) * gamma[c] + beta[c];
    __shared__ float red[128];
    red[c] = z * w2[c];
    __syncthreads();
    for (int s = 64; s > 0; s >>= 1) {
        if (c < s) red[c] += red[c + s];
        __syncthreads();
    }
    if (c == 0) out[e] = 1.f / (1.f + expf(-(red[0] + b2_ptr[0])));
}

// ---------------- launch ----------------
extern "C" void kernel_launch(void* const* d_in, const int* in_sizes, int n_in,
                              void* d_out, int out_size) {
    const int*   edge_index = (const int*)  d_in[0];
    const float* x          = (const float*)d_in[1];
    const int*   eli        = (const int*)  d_in[2];
    const float* gcn_w      = (const float*)d_in[3];
    const float* gcn_b      = (const float*)d_in[4];
    const float* sg_w       = (const float*)d_in[5];
    const float* sg_b       = (const float*)d_in[6];
    const float* bn_gamma   = (const float*)d_in[7];
    const float* bn_beta    = (const float*)d_in[8];
    const float* w_ih_f     = (const float*)d_in[9];
    const float* w_hh_f     = (const float*)d_in[10];
    const float* b_ih_f     = (const float*)d_in[11];
    const float* b_hh_f     = (const float*)d_in[12];
    const float* w_ih_b     = (const float*)d_in[13];
    const float* w_hh_b     = (const float*)d_in[14];
    const float* b_ih_b     = (const float*)d_in[15];
    const float* b_hh_b     = (const float*)d_in[16];
    const float* att_w      = (const float*)d_in[17];
    // d_in[18] = att_b: constant shift over layers -> cancels in softmax
    const float* pred1_w    = (const float*)d_in[19];
    const float* pred1_b    = (const float*)d_in[20];
    const float* pbn_gamma  = (const float*)d_in[21];
    const float* pbn_beta   = (const float*)d_in[22];
    const float* pred2_w    = (const float*)d_in[23];
    const float* pred2_b    = (const float*)d_in[24];
    float* out = (float*)d_out;

    const int E  = in_sizes[0] / 2;
    const int M  = in_sizes[1] / HF;
    const int EL = in_sizes[2] / 2;
    const int* src = edge_index;
    const int* dst = edge_index + E;

    float *HS, *T, *G, *HA, *HB, *Cst, *dinv, *logit, *bsum, *bssq;
    cudaGetSymbolAddress((void**)&HS,    g_HS);
    cudaGetSymbolAddress((void**)&T,     g_T);
    cudaGetSymbolAddress((void**)&G,     g_G);
    cudaGetSymbolAddress((void**)&HA,    g_HA);
    cudaGetSymbolAddress((void**)&HB,    g_HB);
    cudaGetSymbolAddress((void**)&Cst,   g_Cst);
    cudaGetSymbolAddress((void**)&dinv,  g_dinv);
    cudaGetSymbolAddress((void**)&logit, g_logit);
    cudaGetSymbolAddress((void**)&bsum,  g_sum);
    cudaGetSymbolAddress((void**)&bssq,  g_ssq);
    float* Z1 = G + (size_t)64 * 1024 * 1024;

    const size_t lstm_smem = (size_t)(4 * TSTRIDE) * 4 + 128 * 4 + 32 * 4;  // 74368 B
    cudaFuncSetAttribute(lstm_step_kernel,
                         cudaFuncAttributeMaxDynamicSharedMemorySize, (int)lstm_smem);

    dim3 gemm_block(256);
    dim3 tgN128(1, (M + 127) / 128);           // [M,128] tf32 conv GEMMs
    dim3 lstmGrid(GW / 128, (M + 127) / 128);
    dim3 tgPred(1, (EL + 127) / 128);
    int ew_blocks = 4096;
    size_t lstride = (size_t)M * HF;

    // --- degree / normalization ---
    zero_kernel<<<256, 256>>>(dinv, M);
    deg_kernel<<<4096, 256>>>(dst, dinv, E);
    dinv_kernel<<<(M + 255) / 256, 256>>>(dinv, M);

    // --- GCNConv: h0 = prop(x @ W) + b ---
    tgemm_kernel<false, false, false, false><<<tgN128, gemm_block>>>(x, gcn_w, nullptr, T, M, HF, HF);
    prop_init_kernel<true><<<ew_blocks, 256>>>(HS, T, dinv, gcn_b, M);
    prop_edge_kernel<<<(E + 7) / 8, 256>>>(T, HS, src, dst, dinv, E);
    zero_kernel<<<1, 128>>>(bsum, HF);
    zero_kernel<<<1, 128>>>(bssq, HF);
    bn_stats_kernel<true><<<(M + 63) / 64, 128>>>(HS, bsum, bssq, M);
    bn_apply_kernel<true><<<ew_blocks, 256>>>(HS, bsum, bssq, bn_gamma, bn_beta, M);

    // --- SGConv stack ---
    for (int i = 0; i < 3; i++) {
        const float* hin = HS + (size_t)i * lstride;
        float* hout = HS + (size_t)(i + 1) * lstride;
        prop_init_kernel<false><<<ew_blocks, 256>>>(T, hin, dinv, nullptr, M);
        prop_edge_kernel<<<(E + 7) / 8, 256>>>(hin, T, src, dst, dinv, E);
        tgemm_kernel<false, false, false, true><<<tgN128, gemm_block>>>(
            T, sg_w + (size_t)i * HF * HF, sg_b + (size_t)i * HF, hout, M, HF, HF);
        if (i < 2) {
            zero_kernel<<<1, 128>>>(bsum, HF);
            zero_kernel<<<1, 128>>>(bssq, HF);
            bn_stats_kernel<true><<<(M + 63) / 64, 128>>>(hout, bsum, bssq, M);
            bn_apply_kernel<true><<<ew_blocks, 256>>>(hout, bsum, bssq, bn_gamma, bn_beta, M);
        }
    }

    // --- bi-LSTM with fused tf32 double-buffered step kernels ---
    zero_kernel<<<4096, 256>>>(logit, (long long)NLAY * NN);
    zero_kernel<<<4096, 256>>>(HA, (long long)M * HLW);
    zero_kernel<<<4096, 256>>>(Cst, (long long)M * HLW);
    {
        float* hp = HA; float* hn = HB;
        for (int l = 0; l < NLAY; l++) {
            lstm_step_kernel<<<lstmGrid, gemm_block, lstm_smem>>>(
                HS + (size_t)l * lstride, hp, hn, Cst,
                w_ih_f, w_hh_f, b_ih_f, b_hh_f, att_w, logit + (size_t)l * NN, M);
            float* t = hp; hp = hn; hn = t;
        }
    }
    zero_kernel<<<4096, 256>>>(HA, (long long)M * HLW);
    zero_kernel<<<4096, 256>>>(Cst, (long long)M * HLW);
    {
        float* hp = HA; float* hn = HB;
        for (int l = NLAY - 1; l >= 0; l--) {
            lstm_step_kernel<<<lstmGrid, gemm_block, lstm_smem>>>(
                HS + (size_t)l * lstride, hp, hn, Cst,
                w_ih_b, w_hh_b, b_ih_b, b_hh_b, att_w + HLW, logit + (size_t)l * NN, M);
            float* t = hp; hp = hn; hn = t;
        }
    }

    // --- JK attention combine ---
    jk_kernel<<<M, 128>>>(HS, logit, T, M);

    // --- edge predictor ---
    gather_concat_kernel<<<EL, 128>>>(T, eli, eli + EL, G, EL);
    tgemm_kernel<false, false, true, true><<<tgPred, gemm_block>>>(G, pred1_w, pred1_b, Z1, EL, HF, 256);
    zero_kernel<<<1, 128>>>(bsum, HF);
    zero_kernel<<<1, 128>>>(bssq, HF);
    bn_stats_kernel<false><<<(EL + 63) / 64, 128>>>(Z1, bsum, bssq, EL);
    pred_final_kernel<<<EL, 128>>>(Z1, bsum, bssq, pbn_gamma, pbn_beta, pred2_w, pred2_b, out, EL);
}

// round 14
// speedup vs baseline: 1.1298x; 1.1298x over previous
#include <cuda_runtime.h>
#include <math.h>
#include <stdint.h>

// ---------------- problem constants ----------------
#define NN     100000      // nodes
#define NEDGE  1600000     // edges
#define NELBL  200000      // edge-label pairs
#define HF     128         // feature width
#define HLW    256         // LSTM hidden
#define NLAY   4           // layers in jumping knowledge (N_LAYERS+1)
#define GW     1024        // 4*HLW gates
#define BN_EPS 1e-5f

// ---------------- scratch (__device__ globals; total ~975 MB < 2GB link limit) ----
__device__ float g_HS [NLAY * NN * HF];
__device__ float g_T  [NN * HF];
__device__ float g_G  [NN * GW];          // pred gather [EL,256] + Z1
__device__ float g_HA [NN * HLW];
__device__ float g_HB [NN * HLW];
__device__ float g_Cst[NN * HLW];
__device__ float g_dinv[NN];
__device__ float g_logit[NLAY * NN];
__device__ float g_sum[HF];
__device__ float g_ssq[HF];

// ---------------- small utility kernels ----------------
__global__ void zero_kernel(float* p, long long n) {
    long long i = (long long)blockIdx.x * blockDim.x + threadIdx.x;
    long long stride = (long long)gridDim.x * blockDim.x;
    for (; i < n; i += stride) p[i] = 0.f;
}

__global__ void deg_kernel(const int* __restrict__ dst, float* __restrict__ deg, int E) {
    int i = blockIdx.x * blockDim.x + threadIdx.x;
    int stride = gridDim.x * blockDim.x;
    for (; i < E; i += stride) atomicAdd(&deg[dst[i]], 1.f);
}

__global__ void dinv_kernel(float* d, int n) {
    int i = blockIdx.x * blockDim.x + threadIdx.x;
    if (i < n) d[i] = rsqrtf(d[i] + 1.f);
}

template<bool BIAS>
__global__ void prop_init_kernel(float* __restrict__ out, const float* __restrict__ in,
                                 const float* __restrict__ dinv, const float* __restrict__ bias,
                                 int n_nodes) {
    long long i = (long long)blockIdx.x * blockDim.x + threadIdx.x;
    long long total = (long long)n_nodes * HF;
    long long stride = (long long)gridDim.x * blockDim.x;
    for (; i < total; i += stride) {
        int n = (int)(i >> 7);
        int c = (int)(i & 127);
        float dv = dinv[n];
        float v = dv * dv * in[i];
        if (BIAS) v += bias[c];
        out[i] = v;
    }
}

__global__ void prop_edge_kernel(const float* __restrict__ in, float* __restrict__ out,
                                 const int* __restrict__ src, const int* __restrict__ dst,
                                 const float* __restrict__ dinv, int E) {
    int warp = (blockIdx.x * blockDim.x + threadIdx.x) >> 5;
    int lane = threadIdx.x & 31;
    if (warp >= E) return;
    int s = src[warp], d = dst[warp];
    float nrm = dinv[s] * dinv[d];
    const float4* ip = (const float4*)(in + (size_t)s * HF);
    float* op = out + (size_t)d * HF;
    float4 v = ip[lane];
    atomicAdd(op + lane * 4 + 0, nrm * v.x);
    atomicAdd(op + lane * 4 + 1, nrm * v.y);
    atomicAdd(op + lane * 4 + 2, nrm * v.z);
    atomicAdd(op + lane * 4 + 3, nrm * v.w);
}

// ---------------- batchnorm ----------------
template<bool RELU>
__global__ void bn_stats_kernel(const float* __restrict__ X, float* __restrict__ sum,
                                float* __restrict__ ssq, int M) {
    int c = threadIdx.x;
    int r0 = blockIdx.x * 64;
    int r1 = min(r0 + 64, M);
    float s = 0.f, q = 0.f;
    for (int r = r0; r < r1; r++) {
        float v = X[(size_t)r * HF + c];
        if (RELU) v = fmaxf(v, 0.f);
        s += v; q += v * v;
    }
    atomicAdd(&sum[c], s);
    atomicAdd(&ssq[c], q);
}

template<bool RELU>
__global__ void bn_apply_kernel(float* __restrict__ X, const float* __restrict__ sum,
                                const float* __restrict__ ssq, const float* __restrict__ gamma,
                                const float* __restrict__ beta, int M) {
    long long i = (long long)blockIdx.x * blockDim.x + threadIdx.x;
    long long total = (long long)M * HF;
    long long stride = (long long)gridDim.x * blockDim.x;
    float invM = 1.f / (float)M;
    for (; i < total; i += stride) {
        int c = (int)(i & 127);
        float mu = sum[c] * invM;
        float var = ssq[c] * invM - mu * mu;
        float v = X[i];
        if (RELU) v = fmaxf(v, 0.f);
        X[i] = (v - mu) * rsqrtf(var + BN_EPS) * gamma[c] + beta[c];
    }
}

// ---------------- tensor-core helpers ----------------
__device__ __forceinline__ uint32_t f2t(float f) {
    uint32_t u;
    asm("cvt.rna.tf32.f32 %0, %1;" : "=r"(u) : "f"(f));
    return u;
}

__device__ __forceinline__ void mma_tf32(float* c, const uint32_t* a, const uint32_t* b) {
    asm volatile(
        "mma.sync.aligned.m16n8k8.row.col.f32.tf32.tf32.f32 "
        "{%0,%1,%2,%3},{%4,%5,%6,%7},{%8,%9},{%0,%1,%2,%3};"
        : "+f"(c[0]), "+f"(c[1]), "+f"(c[2]), "+f"(c[3])
        : "r"(a[0]), "r"(a[1]), "r"(a[2]), "r"(a[3]), "r"(b[0]), "r"(b[1]));
}

__device__ __forceinline__ float sigmoidf(float x) { return 1.f / (1.f + expf(-x)); }

// ---------------- generic tf32 GEMM (conv stack + pred1) ----------------
template<bool BT, bool ACC, bool RELU, bool BIAS>
__global__ void __launch_bounds__(256) tgemm_kernel(
    const float* __restrict__ A, const float* __restrict__ B,
    const float* __restrict__ bias, float* __restrict__ C,
    int M, int N, int K) {
    __shared__ uint32_t As[128][36];
    __shared__ uint32_t Bs[128][36];
    int tid = threadIdx.x;
    int warp = tid >> 5, lane = tid & 31;
    int gid = lane >> 2, tig = lane & 3;
    int wm = (warp & 1) * 64;
    int wn = (warp >> 1) * 32;
    int row0 = blockIdx.y * 128;
    int col0 = blockIdx.x * 128;

    float c[4][4][4] = {};

    for (int k0 = 0; k0 < K; k0 += 32) {
        {
            int r = tid >> 3;
            int cc = (tid & 7) * 4;
            #pragma unroll
            for (int p = 0; p < 4; p++) {
                int rr = p * 32 + r;
                int gr = row0 + rr;
                float4 v = (gr < M) ? *(const float4*)(A + (size_t)gr * K + k0 + cc)
                                    : make_float4(0.f, 0.f, 0.f, 0.f);
                *(uint4*)&As[rr][cc] = make_uint4(f2t(v.x), f2t(v.y), f2t(v.z), f2t(v.w));
            }
        }
        if (BT) {
            int r = tid >> 3;
            int cc = (tid & 7) * 4;
            #pragma unroll
            for (int p = 0; p < 4; p++) {
                int rr = p * 32 + r;
                float4 v = *(const float4*)(B + (size_t)(col0 + rr) * K + k0 + cc);
                *(uint4*)&Bs[rr][cc] = make_uint4(f2t(v.x), f2t(v.y), f2t(v.z), f2t(v.w));
            }
        } else {
            int r = tid >> 5;
            int cc = (tid & 31) * 4;
            #pragma unroll
            for (int p = 0; p < 4; p++) {
                int kk = p * 8 + r;
                float4 v = *(const float4*)(B + (size_t)(k0 + kk) * N + col0 + cc);
                Bs[cc + 0][kk] = f2t(v.x);
                Bs[cc + 1][kk] = f2t(v.y);
                Bs[cc + 2][kk] = f2t(v.z);
                Bs[cc + 3][kk] = f2t(v.w);
            }
        }
        __syncthreads();
        #pragma unroll
        for (int ks = 0; ks < 4; ks++) {
            int kk = ks * 8;
            uint32_t a[4][4], b[4][2];
            #pragma unroll
            for (int mi = 0; mi < 4; mi++) {
                int rr = wm + mi * 16 + gid;
                a[mi][0] = As[rr][kk + tig];
                a[mi][1] = As[rr + 8][kk + tig];
                a[mi][2] = As[rr][kk + tig + 4];
                a[mi][3] = As[rr + 8][kk + tig + 4];
            }
            #pragma unroll
            for (int ni = 0; ni < 4; ni++) {
                int nn = wn + ni * 8 + gid;
                b[ni][0] = Bs[nn][kk + tig];
                b[ni][1] = Bs[nn][kk + tig + 4];
            }
            #pragma unroll
            for (int mi = 0; mi < 4; mi++)
                #pragma unroll
                for (int ni = 0; ni < 4; ni++)
                    mma_tf32(c[mi][ni], a[mi], b[ni]);
        }
        __syncthreads();
    }

    #pragma unroll
    for (int mi = 0; mi < 4; mi++) {
        int r_lo = row0 + wm + mi * 16 + gid;
        int r_hi = r_lo + 8;
        #pragma unroll
        for (int ni = 0; ni < 4; ni++) {
            int cb = col0 + wn + ni * 8 + tig * 2;
            #pragma unroll
            for (int q = 0; q < 4; q++) {
                int gr = (q < 2) ? r_lo : r_hi;
                int gc = cb + (q & 1);
                if (gr >= M) continue;
                float v = c[mi][ni][q];
                if (BIAS) v += bias[gc];
                size_t off = (size_t)gr * N + gc;
                if (ACC) v += C[off];
                if (RELU) v = fmaxf(v, 0.f);
                C[off] = v;
            }
        }
    }
}

// ---------------- fused LSTM step (tf32, reg-prefetch; FIRST/LAST special) --
// Round-12 proven design. FIRST: h_prev=0, c=0 -> skip the hh-GEMM entirely
// (K=128, 4 tiles instead of 12) and skip the Cst read; cell c = sig(i)*tanh(g).
// LAST: skip Hnext/Cst stores (dead). bias_s = b_ih+b_hh always (h=0 exact).
template<bool FIRST, bool LAST>
__global__ void __launch_bounds__(256) lstm_step_kernel(
    const float* __restrict__ X, const float* __restrict__ Hprev,
    float* __restrict__ Hnext, float* __restrict__ Cst,
    const float* __restrict__ w_ih, const float* __restrict__ w_hh,
    const float* __restrict__ b_ih, const float* __restrict__ b_hh,
    const float* __restrict__ attw, float* __restrict__ logit, int M) {
    __shared__ uint32_t As[128][36];
    __shared__ uint32_t Bs[128][36];
    __shared__ float bias_s[128];
    __shared__ float attw_s[32];

    const int NT = FIRST ? 4 : 12;   // K tiles of 32

    int tid = threadIdx.x;
    int warp = tid >> 5, lane = tid & 31;
    int gid = lane >> 2, tig = lane & 3;
    int wm = (warp & 1) * 64;
    int wn = (warp >> 1) * 32;
    int row0 = blockIdx.y * 128;
    int col0 = blockIdx.x * 128;

    if (tid < 128) {
        int oc = col0 + tid;
        int pr = (oc & 3) * 256 + (oc >> 2);
        bias_s[tid] = b_ih[pr] + b_hh[pr];
        if (tid < 32) attw_s[tid] = attw[(col0 >> 2) + tid];
    }

    int ldr = tid >> 3;              // 0..31
    int ldc = (tid & 7) * 4;         // 0,4,...,28
    float4 ra[4], rb[4];
    int prw[4];
    #pragma unroll
    for (int p = 0; p < 4; p++) {
        int oc = col0 + p * 32 + ldr;
        prw[p] = (oc & 3) * 256 + (oc >> 2);
    }

    float c[4][4][4] = {};

    // ---- prologue: fetch tile 0 into regs ----
    #pragma unroll
    for (int p = 0; p < 4; p++) {
        int gr = row0 + p * 32 + ldr;
        ra[p] = (gr < M) ? *(const float4*)(X + (size_t)gr * HF + ldc)
                         : make_float4(0.f, 0.f, 0.f, 0.f);
        rb[p] = *(const float4*)(w_ih + (size_t)prw[p] * HF + ldc);
    }
    __syncthreads();   // bias_s/attw_s ready; smem free
    #pragma unroll
    for (int p = 0; p < 4; p++) {
        int rr = p * 32 + ldr;
        *(float4*)&As[rr][ldc] = ra[p];
        *(float4*)&Bs[rr][ldc] = rb[p];
    }
    __syncthreads();

    for (int it = 0; it < NT; it++) {
        // prefetch tile it+1 into registers (overlaps with MMAs below)
        if (it + 1 < NT) {
            int k0 = (it + 1) * 32;
            const float* Asrc;
            int Ak, kk0;
            if (k0 < 128) { Asrc = X; Ak = HF; kk0 = k0; }
            else          { Asrc = Hprev; Ak = HLW; kk0 = k0 - 128; }
            #pragma unroll
            for (int p = 0; p < 4; p++) {
                int gr = row0 + p * 32 + ldr;
                ra[p] = (gr < M) ? *(const float4*)(Asrc + (size_t)gr * Ak + kk0 + ldc)
                                 : make_float4(0.f, 0.f, 0.f, 0.f);
                rb[p] = (k0 < 128)
                    ? *(const float4*)(w_ih + (size_t)prw[p] * HF + k0 + ldc)
                    : *(const float4*)(w_hh + (size_t)prw[p] * HLW + (k0 - 128) + ldc);
            }
        }
        // compute on current smem tile
        #pragma unroll
        for (int ks = 0; ks < 4; ks++) {
            int kk = ks * 8;
            uint32_t a[4][4], b[4][2];
            #pragma unroll
            for (int mi = 0; mi < 4; mi++) {
                int rr = wm + mi * 16 + gid;
                a[mi][0] = As[rr][kk + tig];
                a[mi][1] = As[rr + 8][kk + tig];
                a[mi][2] = As[rr][kk + tig + 4];
                a[mi][3] = As[rr + 8][kk + tig + 4];
            }
            #pragma unroll
            for (int ni = 0; ni < 4; ni++) {
                int nn = wn + ni * 8 + gid;
                b[ni][0] = Bs[nn][kk + tig];
                b[ni][1] = Bs[nn][kk + tig + 4];
            }
            #pragma unroll
            for (int mi = 0; mi < 4; mi++)
                #pragma unroll
                for (int ni = 0; ni < 4; ni++)
                    mma_tf32(c[mi][ni], a[mi], b[ni]);
        }
        __syncthreads();    // all warps done reading smem
        if (it + 1 < NT) {
            #pragma unroll
            for (int p = 0; p < 4; p++) {
                int rr = p * 32 + ldr;
                *(float4*)&As[rr][ldc] = ra[p];
                *(float4*)&Bs[rr][ldc] = rb[p];
            }
            __syncthreads();
        }
    }

    // --- fused LSTM cell epilogue ---
    int odd = tig & 1;
    #pragma unroll
    for (int mi = 0; mi < 4; mi++) {
        int r_lo = row0 + wm + mi * 16 + gid;
        int row = odd ? (r_lo + 8) : r_lo;
        float lp = 0.f;
        #pragma unroll
        for (int ni = 0; ni < 4; ni++) {
            int cb = wn + ni * 8 + tig * 2;
            float q0 = c[mi][ni][0] + bias_s[cb];
            float q1 = c[mi][ni][1] + bias_s[cb + 1];
            float q2 = c[mi][ni][2] + bias_s[cb];
            float q3 = c[mi][ni][3] + bias_s[cb + 1];
            float r0 = __shfl_xor_sync(0xFFFFFFFFu, odd ? q0 : q2, 1);
            float r1 = __shfl_xor_sync(0xFFFFFFFFu, odd ? q1 : q3, 1);
            float gi, gf, gg, go;
            int jl;
            if (!odd) { gi = q0; gf = q1; gg = r0; go = r1; jl = cb >> 2; }
            else      { gi = r0; gf = r1; gg = q2; go = q3; jl = (cb - 2) >> 2; }
            if (row < M) {
                int jg = (col0 >> 2) + jl;
                size_t off = (size_t)row * HLW + jg;
                float cn;
                if (FIRST) cn = sigmoidf(gi) * tanhf(gg);           // c_prev = 0
                else       cn = sigmoidf(gf) * Cst[off] + sigmoidf(gi) * tanhf(gg);
                float hn = sigmoidf(go) * tanhf(cn);
                if (!LAST) {
                    Cst[off] = cn;
                    Hnext[off] = hn;
                }
                lp += hn * attw_s[jl];
            }
        }
        lp += __shfl_xor_sync(0xFFFFFFFFu, lp, 2);
        if (tig < 2 && row < M) atomicAdd(&logit[row], lp);
    }
}

// ---------------- jumping-knowledge attention combine ----------------
__global__ void jk_kernel(const float* __restrict__ HS, const float* __restrict__ logit,
                          float* __restrict__ jk, int M) {
    int n = blockIdx.x;
    int c = threadIdx.x;  // 128
    float l0 = logit[0 * NN + n], l1 = logit[1 * NN + n];
    float l2 = logit[2 * NN + n], l3 = logit[3 * NN + n];
    float m = fmaxf(fmaxf(l0, l1), fmaxf(l2, l3));
    float e0 = expf(l0 - m), e1 = expf(l1 - m), e2 = expf(l2 - m), e3 = expf(l3 - m);
    float inv = 1.f / (e0 + e1 + e2 + e3);
    size_t off = (size_t)n * HF + c;
    size_t ls = (size_t)M * HF;
    float v = e0 * HS[off] + e1 * HS[ls + off] + e2 * HS[2 * ls + off] + e3 * HS[3 * ls + off];
    jk[off] = v * inv;
}

// ---------------- edge predictor ----------------
__global__ void gather_concat_kernel(const float* __restrict__ jk, const int* __restrict__ rows,
                                     const int* __restrict__ cols, float* __restrict__ out, int EL) {
    int e = blockIdx.x;
    int t = threadIdx.x;  // 128
    if (e >= EL) return;
    out[(size_t)e * 256 + t]       = jk[(size_t)rows[e] * HF + t];
    out[(size_t)e * 256 + 128 + t] = jk[(size_t)cols[e] * HF + t];
}

__global__ void pred_final_kernel(const float* __restrict__ Z1, const float* __restrict__ sum,
                                  const float* __restrict__ ssq, const float* __restrict__ gamma,
                                  const float* __restrict__ beta, const float* __restrict__ w2,
                                  const float* __restrict__ b2_ptr, float* __restrict__ out, int EL) {
    int e = blockIdx.x;
    int c = threadIdx.x;  // 128
    float invM = 1.f / (float)EL;
    float mu = sum[c] * invM;
    float var = ssq[c] * invM - mu * mu;
    float z = (Z1[(size_t)e * HF + c] - mu) * rsqrtf(var + BN_EPS) * gamma[c] + beta[c];
    __shared__ float red[128];
    red[c] = z * w2[c];
    __syncthreads();
    for (int s = 64; s > 0; s >>= 1) {
        if (c < s) red[c] += red[c + s];
        __syncthreads();
    }
    if (c == 0) out[e] = 1.f / (1.f + expf(-(red[0] + b2_ptr[0])));
}

// ---------------- launch ----------------
extern "C" void kernel_launch(void* const* d_in, const int* in_sizes, int n_in,
                              void* d_out, int out_size) {
    const int*   edge_index = (const int*)  d_in[0];
    const float* x          = (const float*)d_in[1];
    const int*   eli        = (const int*)  d_in[2];
    const float* gcn_w      = (const float*)d_in[3];
    const float* gcn_b      = (const float*)d_in[4];
    const float* sg_w       = (const float*)d_in[5];
    const float* sg_b       = (const float*)d_in[6];
    const float* bn_gamma   = (const float*)d_in[7];
    const float* bn_beta    = (const float*)d_in[8];
    const float* w_ih_f     = (const float*)d_in[9];
    const float* w_hh_f     = (const float*)d_in[10];
    const float* b_ih_f     = (const float*)d_in[11];
    const float* b_hh_f     = (const float*)d_in[12];
    const float* w_ih_b     = (const float*)d_in[13];
    const float* w_hh_b     = (const float*)d_in[14];
    const float* b_ih_b     = (const float*)d_in[15];
    const float* b_hh_b     = (const float*)d_in[16];
    const float* att_w      = (const float*)d_in[17];
    // d_in[18] = att_b: constant shift over layers -> cancels in softmax
    const float* pred1_w    = (const float*)d_in[19];
    const float* pred1_b    = (const float*)d_in[20];
    const float* pbn_gamma  = (const float*)d_in[21];
    const float* pbn_beta   = (const float*)d_in[22];
    const float* pred2_w    = (const float*)d_in[23];
    const float* pred2_b    = (const float*)d_in[24];
    float* out = (float*)d_out;

    const int E  = in_sizes[0] / 2;
    const int M  = in_sizes[1] / HF;
    const int EL = in_sizes[2] / 2;
    const int* src = edge_index;
    const int* dst = edge_index + E;

    float *HS, *T, *G, *HA, *HB, *Cst, *dinv, *logit, *bsum, *bssq;
    cudaGetSymbolAddress((void**)&HS,    g_HS);
    cudaGetSymbolAddress((void**)&T,     g_T);
    cudaGetSymbolAddress((void**)&G,     g_G);
    cudaGetSymbolAddress((void**)&HA,    g_HA);
    cudaGetSymbolAddress((void**)&HB,    g_HB);
    cudaGetSymbolAddress((void**)&Cst,   g_Cst);
    cudaGetSymbolAddress((void**)&dinv,  g_dinv);
    cudaGetSymbolAddress((void**)&logit, g_logit);
    cudaGetSymbolAddress((void**)&bsum,  g_sum);
    cudaGetSymbolAddress((void**)&bssq,  g_ssq);
    float* Z1 = G + (size_t)64 * 1024 * 1024;

    dim3 gemm_block(256);
    dim3 tgN128(1, (M + 127) / 128);           // [M,128] tf32 conv GEMMs
    dim3 lstmGrid(GW / 128, (M + 127) / 128);
    dim3 tgPred(1, (EL + 127) / 128);
    int ew_blocks = 4096;
    size_t lstride = (size_t)M * HF;

    // --- degree / normalization ---
    zero_kernel<<<256, 256>>>(dinv, M);
    deg_kernel<<<4096, 256>>>(dst, dinv, E);
    dinv_kernel<<<(M + 255) / 256, 256>>>(dinv, M);

    // --- GCNConv: h0 = prop(x @ W) + b ---
    tgemm_kernel<false, false, false, false><<<tgN128, gemm_block>>>(x, gcn_w, nullptr, T, M, HF, HF);
    prop_init_kernel<true><<<ew_blocks, 256>>>(HS, T, dinv, gcn_b, M);
    prop_edge_kernel<<<(E + 7) / 8, 256>>>(T, HS, src, dst, dinv, E);
    zero_kernel<<<1, 128>>>(bsum, HF);
    zero_kernel<<<1, 128>>>(bssq, HF);
    bn_stats_kernel<true><<<(M + 63) / 64, 128>>>(HS, bsum, bssq, M);
    bn_apply_kernel<true><<<ew_blocks, 256>>>(HS, bsum, bssq, bn_gamma, bn_beta, M);

    // --- SGConv stack ---
    for (int i = 0; i < 3; i++) {
        const float* hin = HS + (size_t)i * lstride;
        float* hout = HS + (size_t)(i + 1) * lstride;
        prop_init_kernel<false><<<ew_blocks, 256>>>(T, hin, dinv, nullptr, M);
        prop_edge_kernel<<<(E + 7) / 8, 256>>>(hin, T, src, dst, dinv, E);
        tgemm_kernel<false, false, false, true><<<tgN128, gemm_block>>>(
            T, sg_w + (size_t)i * HF * HF, sg_b + (size_t)i * HF, hout, M, HF, HF);
        if (i < 2) {
            zero_kernel<<<1, 128>>>(bsum, HF);
            zero_kernel<<<1, 128>>>(bssq, HF);
            bn_stats_kernel<true><<<(M + 63) / 64, 128>>>(hout, bsum, bssq, M);
            bn_apply_kernel<true><<<ew_blocks, 256>>>(hout, bsum, bssq, bn_gamma, bn_beta, M);
        }
    }

    // --- bi-LSTM: FIRST step skips hh-GEMM (h=0,c=0); LAST skips state stores ---
    zero_kernel<<<4096, 256>>>(logit, (long long)NLAY * NN);
    // forward: layers 0(FIRST),1,2,3(LAST)
    lstm_step_kernel<true, false><<<lstmGrid, gemm_block>>>(
        HS, nullptr, HA, Cst, w_ih_f, w_hh_f, b_ih_f, b_hh_f, att_w, logit, M);
    lstm_step_kernel<false, false><<<lstmGrid, gemm_block>>>(
        HS + lstride, HA, HB, Cst, w_ih_f, w_hh_f, b_ih_f, b_hh_f, att_w, logit + (size_t)1 * NN, M);
    lstm_step_kernel<false, false><<<lstmGrid, gemm_block>>>(
        HS + 2 * lstride, HB, HA, Cst, w_ih_f, w_hh_f, b_ih_f, b_hh_f, att_w, logit + (size_t)2 * NN, M);
    lstm_step_kernel<false, true><<<lstmGrid, gemm_block>>>(
        HS + 3 * lstride, HA, HB, Cst, w_ih_f, w_hh_f, b_ih_f, b_hh_f, att_w, logit + (size_t)3 * NN, M);
    // backward: layers 3(FIRST),2,1,0(LAST)
    lstm_step_kernel<true, false><<<lstmGrid, gemm_block>>>(
        HS + 3 * lstride, nullptr, HA, Cst, w_ih_b, w_hh_b, b_ih_b, b_hh_b, att_w + HLW, logit + (size_t)3 * NN, M);
    lstm_step_kernel<false, false><<<lstmGrid, gemm_block>>>(
        HS + 2 * lstride, HA, HB, Cst, w_ih_b, w_hh_b, b_ih_b, b_hh_b, att_w + HLW, logit + (size_t)2 * NN, M);
    lstm_step_kernel<false, false><<<lstmGrid, gemm_block>>>(
        HS + lstride, HB, HA, Cst, w_ih_b, w_hh_b, b_ih_b, b_hh_b, att_w + HLW, logit + (size_t)1 * NN, M);
    lstm_step_kernel<false, true><<<lstmGrid, gemm_block>>>(
        HS, HA, HB, Cst, w_ih_b, w_hh_b, b_ih_b, b_hh_b, att_w + HLW, logit, M);

    // --- JK attention combine ---
    jk_kernel<<<M, 128>>>(HS, logit, T, M);

    // --- edge predictor ---
    gather_concat_kernel<<<EL, 128>>>(T, eli, eli + EL, G, EL);
    tgemm_kernel<false, false, true, true><<<tgPred, gemm_block>>>(G, pred1_w, pred1_b, Z1, EL, HF, 256);
    zero_kernel<<<1, 128>>>(bsum, HF);
    zero_kernel<<<1, 128>>>(bssq, HF);
    bn_stats_kernel<false><<<(EL + 63) / 64, 128>>>(Z1, bsum, bssq, EL);
    pred_final_kernel<<<EL, 128>>>(Z1, bsum, bssq, pbn_gamma, pbn_beta, pred2_w, pred2_b, out, EL);
}